// round 1
// baseline (speedup 1.0000x reference)
#include <cuda_runtime.h>
#include <math.h>
#include <stdint.h>

// Problem constants (fixed by the reference)
#define Nn 262144
#define Dd 64
#define Kk 64
#define LOG2PI_F 1.83787706640934548356f
#define PLV0 (-2.0f)   // prior_logvar_0

#define TPB 256
#define RPB 128        // rows per block
#define XSTRIDE 68     // padded row stride for X tile in smem (bank-friendly)

#define SMEM_FLOATS (RPB*XSTRIDE + 2*Dd*Kk + 3*64)
#define SMEM_BYTES  (SMEM_FLOATS * 4)

// Precomputed small matrices / vectors (device globals: no allocation allowed)
__device__ float  g_A[Dd*Kk];    // [d][k] = phi_d * exp(-clip(logvar_kd))
__device__ float  g_B2[Dd*Kk];   // [d][k] = -2 * mu_kd * A[d][k]
__device__ float  g_offs[Kk];    // -0.5*(const_k + sum_d mu^2 * A)
__device__ float  g_logpi[Kk];   // log(softmax(pi)+1e-9)
__device__ float  g_wbg[Dd];     // (1-phi_d) * exp(-PLV0)
__device__ float  g_C0;          // sum_d (1-phi_d)*(LOG2PI+PLV0)
__device__ double g_kl;          // kl_phi * N
__device__ double g_lse;         // sum_n logsumexp_k (accumulated)

// ---------------------------------------------------------------------------
// Kernel 1: tiny precompute (64 threads). Also resets g_lse each launch so
// graph replays are deterministic, and writes q_phi to out[1..64].
// ---------------------------------------------------------------------------
__global__ void precompute_kernel(const float* __restrict__ u_noise,
                                  const float* __restrict__ phi_logits,
                                  const float* __restrict__ q_mu,
                                  const float* __restrict__ q_logvar,
                                  const float* __restrict__ pi_logits,
                                  const float* __restrict__ prior_p,
                                  float* __restrict__ out)
{
    __shared__ float phi_s[Dd];
    __shared__ float pil_s[Kk];
    __shared__ float rbuf[64];
    int t = threadIdx.x;  // 0..63

    // per-dimension gate phi (Gumbel-sigmoid, TEMPERATURE = 1)
    float u   = u_noise[t];
    float g   = -logf(-logf(u + 1e-9f) + 1e-9f);
    float pl  = phi_logits[t];
    float phi = 1.0f / (1.0f + expf(-(pl + g)));
    phi_s[t]  = phi;

    // q_phi output + KL contribution
    float qphi = 1.0f / (1.0f + expf(-pl));
    qphi = fminf(fmaxf(qphi, 1e-6f), 1.0f - 1e-6f);
    out[1 + t] = qphi;
    float p = fminf(fmaxf(prior_p[t], 1e-6f), 1.0f - 1e-6f);
    float klc = qphi * (logf(qphi) - logf(p))
              + (1.0f - qphi) * (logf(1.0f - qphi) - logf(1.0f - p));

    // background-term constants
    g_wbg[t]  = (1.0f - phi) * expf(-PLV0);
    float c0c = (1.0f - phi) * (LOG2PI_F + PLV0);
    pil_s[t]  = pi_logits[t];

    // reduce KL over D
    rbuf[t] = klc; __syncthreads();
    for (int s = 32; s > 0; s >>= 1) { if (t < s) rbuf[t] += rbuf[t + s]; __syncthreads(); }
    if (t == 0) g_kl = (double)rbuf[0] * (double)Nn;
    __syncthreads();
    // reduce C0 over D
    rbuf[t] = c0c; __syncthreads();
    for (int s = 32; s > 0; s >>= 1) { if (t < s) rbuf[t] += rbuf[t + s]; __syncthreads(); }
    if (t == 0) { g_C0 = rbuf[0]; g_lse = 0.0; }
    __syncthreads();

    // log softmax(pi)+1e-9 (each thread recomputes from smem; K=64, cheap)
    float m = -3.4e38f;
    #pragma unroll 8
    for (int k = 0; k < Kk; k++) m = fmaxf(m, pil_s[k]);
    float ssum = 0.f;
    #pragma unroll 8
    for (int k = 0; k < Kk; k++) ssum += expf(pil_s[k] - m);
    g_logpi[t] = logf(expf(pil_s[t] - m) / ssum + 1e-9f);

    // per-cluster matrices: thread t handles cluster k = t
    int k = t;
    float ck = 0.f, c2 = 0.f;
    for (int d = 0; d < Dd; d++) {
        float lv = fminf(fmaxf(q_logvar[k*Dd + d], -5.0f), 5.0f);
        float iv = expf(-lv);
        float a  = phi_s[d] * iv;
        float mu = q_mu[k*Dd + d];
        g_A [d*Kk + k] = a;
        g_B2[d*Kk + k] = -2.0f * mu * a;
        c2 += mu * mu * a;
        ck += phi_s[d] * (LOG2PI_F + lv);
    }
    g_offs[k] = -0.5f * (ck + c2);
}

// ---------------------------------------------------------------------------
// Kernel 2: fused main pass. One block = 128 rows x all 64 clusters.
// Thread micro-tile: 4 rows x 8 clusters (32 fp32 accumulators).
// Fuses: quad GEMM + background quad + lp write + logsumexp + loss partial.
// ---------------------------------------------------------------------------
__global__ void __launch_bounds__(TPB)
main_kernel(const float* __restrict__ X, float* __restrict__ out)
{
    extern __shared__ float smem[];
    float* X_s    = smem;                  // RPB * XSTRIDE
    float* A_s    = X_s + RPB * XSTRIDE;   // Dd*Kk, [d][k]
    float* B2_s   = A_s + Dd * Kk;         // Dd*Kk, [d][k]
    float* wbg_s  = B2_s + Dd * Kk;        // Dd
    float* offs_s = wbg_s + Dd;            // Kk
    float* lpi_s  = offs_s + Kk;           // Kk
    __shared__ double warpsum[TPB / 32];

    int tid = threadIdx.x;
    int n0  = blockIdx.x * RPB;

    // stage A / B2 (coalesced float4) + small vectors
    {
        const float4* Ag = (const float4*)g_A;
        const float4* Bg = (const float4*)g_B2;
        float4* A4 = (float4*)A_s;
        float4* B4 = (float4*)B2_s;
        #pragma unroll
        for (int i = 0; i < (Dd*Kk/4)/TPB; i++) {
            A4[tid + TPB*i] = Ag[tid + TPB*i];
            B4[tid + TPB*i] = Bg[tid + TPB*i];
        }
        if (tid < 64) {
            wbg_s[tid]  = g_wbg[tid];
            offs_s[tid] = g_offs[tid];
            lpi_s[tid]  = g_logpi[tid];
        }
    }
    // stage X tile: 128 rows x 64 floats, coalesced float4 loads
    {
        int q = tid & 15, r0 = tid >> 4;
        #pragma unroll
        for (int it = 0; it < RPB/16; it++) {
            int r = r0 + 16*it;
            float4 v = *(const float4*)(X + (size_t)(n0 + r)*Dd + q*4);
            *(float4*)(X_s + r*XSTRIDE + q*4) = v;
        }
    }
    __syncthreads();

    const int tcol  = tid & 7;     // cluster group 0..7
    const int trow  = tid >> 3;    // 0..31
    const int kbase = tcol * 8;

    float acc[4][8];
    float accbg[4];
    #pragma unroll
    for (int i = 0; i < 4; i++) {
        accbg[i] = 0.f;
        #pragma unroll
        for (int j = 0; j < 8; j++) acc[i][j] = 0.f;
    }

    #pragma unroll 4
    for (int d = 0; d < Dd; d++) {
        float4 a0 = *(const float4*)(A_s  + d*Kk + kbase);
        float4 a1 = *(const float4*)(A_s  + d*Kk + kbase + 4);
        float4 b0 = *(const float4*)(B2_s + d*Kk + kbase);
        float4 b1 = *(const float4*)(B2_s + d*Kk + kbase + 4);
        float av[8] = {a0.x, a0.y, a0.z, a0.w, a1.x, a1.y, a1.z, a1.w};
        float bv[8] = {b0.x, b0.y, b0.z, b0.w, b1.x, b1.y, b1.z, b1.w};
        float w = wbg_s[d];
        #pragma unroll
        for (int i = 0; i < 4; i++) {
            float x  = X_s[(trow + 32*i)*XSTRIDE + d];
            float x2 = x * x;
            accbg[i] = fmaf(w, x2, accbg[i]);
            #pragma unroll
            for (int j = 0; j < 8; j++)
                acc[i][j] = fmaf(x2, av[j], fmaf(x, bv[j], acc[i][j]));
        }
    }

    const float C0 = g_C0;
    double mysum = 0.0;
    #pragma unroll
    for (int i = 0; i < 4; i++) {
        int n = n0 + trow + 32*i;
        float lpbg = -0.5f * (C0 + accbg[i]);
        float lp[8];
        float m = -3.4e38f;
        #pragma unroll
        for (int j = 0; j < 8; j++) {
            lp[j] = fmaf(-0.5f, acc[i][j], offs_s[kbase + j]) + lpbg;
            m = fmaxf(m, lp[j] + lpi_s[kbase + j]);
        }
        // write log_p (output region starts at float offset 65 -> scalar stores)
        float* o = out + 65 + (size_t)n * Kk + kbase;
        #pragma unroll
        for (int j = 0; j < 8; j++) o[j] = lp[j];
        // logsumexp over 64 clusters: local 8 + shuffle across the 8 lanes of this row
        #pragma unroll
        for (int s = 1; s < 8; s <<= 1) m = fmaxf(m, __shfl_xor_sync(0xffffffffu, m, s));
        float se = 0.f;
        #pragma unroll
        for (int j = 0; j < 8; j++) se += expf(lp[j] + lpi_s[kbase + j] - m);
        #pragma unroll
        for (int s = 1; s < 8; s <<= 1) se += __shfl_xor_sync(0xffffffffu, se, s);
        if (tcol == 0) mysum += (double)(m + logf(se));
    }

    // block reduce loss partial -> one double atomic per block
    #pragma unroll
    for (int s = 16; s > 0; s >>= 1) mysum += __shfl_xor_sync(0xffffffffu, mysum, s);
    if ((tid & 31) == 0) warpsum[tid >> 5] = mysum;
    __syncthreads();
    if (tid == 0) {
        double s = 0.0;
        #pragma unroll
        for (int w = 0; w < TPB/32; w++) s += warpsum[w];
        atomicAdd(&g_lse, s);
    }
}

// ---------------------------------------------------------------------------
// Kernel 3: finalize loss = -LL + kl = kl - sum(lse)
// ---------------------------------------------------------------------------
__global__ void finalize_kernel(float* __restrict__ out)
{
    out[0] = (float)(g_kl - g_lse);
}

// ---------------------------------------------------------------------------
extern "C" void kernel_launch(void* const* d_in, const int* in_sizes, int n_in,
                              void* d_out, int out_size)
{
    const float* X   = (const float*)d_in[0];
    const float* u   = (const float*)d_in[1];
    const float* pl  = (const float*)d_in[2];
    const float* mu  = (const float*)d_in[3];
    const float* lv  = (const float*)d_in[4];
    const float* pi  = (const float*)d_in[5];
    const float* pp  = (const float*)d_in[6];
    float* out = (float*)d_out;

    // >48KB dynamic smem needs the attribute; idempotent, safe under capture.
    cudaFuncSetAttribute(main_kernel,
                         cudaFuncAttributeMaxDynamicSharedMemorySize, SMEM_BYTES);

    precompute_kernel<<<1, 64>>>(u, pl, mu, lv, pi, pp, out);
    main_kernel<<<Nn / RPB, TPB, SMEM_BYTES>>>(X, out);
    finalize_kernel<<<1, 1>>>(out);
}

// round 3
// speedup vs baseline: 2.8666x; 2.8666x over previous
#include <cuda_runtime.h>
#include <math.h>
#include <stdint.h>

// ---------------- problem constants ----------------
#define Nn 262144
#define Dd 64
#define Kk 64
#define NB 72            // MMA N: 64 clusters + 1 background col + 7 pad
#define TM 128           // rows per CTA
#define NTILES (Nn/TM)   // 2048
#define TPB 256
#define LOG2PI_F 1.83787706640934548356f
#define PLV0 (-2.0f)

// ---------------- device globals (no allocs allowed) ----------------
__device__ float  g_Bmat[NB*128];   // [n][k]: k<64 -> -2*mu*a ; k>=64 -> a (col 64 = bg wts)
__device__ float  g_offs[Kk];
__device__ float  g_logpi[Kk];
__device__ float  g_C0;
__device__ double g_kl;
__device__ double g_lse;

__device__ __forceinline__ float tf32r(float x) {
    float r; asm("cvt.rna.tf32.f32 %0, %1;" : "=f"(r) : "f"(x)); return r;
}

__device__ __forceinline__ void mma8(float c[4],
                                     uint32_t a0, uint32_t a1, uint32_t a2, uint32_t a3,
                                     uint32_t b0, uint32_t b1) {
    asm volatile("mma.sync.aligned.m16n8k8.row.col.f32.tf32.tf32.f32 "
        "{%0,%1,%2,%3}, {%4,%5,%6,%7}, {%8,%9}, {%0,%1,%2,%3};"
        : "+f"(c[0]), "+f"(c[1]), "+f"(c[2]), "+f"(c[3])
        : "r"(a0), "r"(a1), "r"(a2), "r"(a3), "r"(b0), "r"(b1));
}

// ---------------------------------------------------------------------------
// Kernel 1: precompute (1 block x 1024 threads).
// ---------------------------------------------------------------------------
__global__ void precompute_kernel(const float* __restrict__ u_noise,
                                  const float* __restrict__ phi_logits,
                                  const float* __restrict__ q_mu,
                                  const float* __restrict__ q_logvar,
                                  const float* __restrict__ pi_logits,
                                  const float* __restrict__ prior_p,
                                  float* __restrict__ out)
{
    __shared__ float phi_s[64], wbg_s[64], red[64], red2[64], pil_s[64];
    __shared__ float obuf[Kk*Dd];
    int t = threadIdx.x;

    if (t < 64) {
        float uu  = u_noise[t];
        float g   = -logf(-logf(uu + 1e-9f) + 1e-9f);
        float pl  = phi_logits[t];
        float phi = 1.0f / (1.0f + expf(-(pl + g)));
        phi_s[t]  = phi;
        float qphi = 1.0f / (1.0f + expf(-pl));
        qphi = fminf(fmaxf(qphi, 1e-6f), 1.0f - 1e-6f);
        out[1 + t] = qphi;
        float p = fminf(fmaxf(prior_p[t], 1e-6f), 1.0f - 1e-6f);
        red[t]  = qphi * (logf(qphi) - logf(p))
                + (1.0f - qphi) * (logf(1.0f - qphi) - logf(1.0f - p));
        wbg_s[t] = (1.0f - phi) * expf(-PLV0);
        red2[t]  = (1.0f - phi) * (LOG2PI_F + PLV0);
        pil_s[t] = pi_logits[t];
    }
    __syncthreads();
    if (t == 0) {
        float kl = 0.f, c0 = 0.f;
        for (int i = 0; i < 64; i++) { kl += red[i]; c0 += red2[i]; }
        g_kl  = (double)kl * (double)Nn;
        g_C0  = c0;
        g_lse = 0.0;
    }
    if (t < 64) {
        float m = -3.4e38f;
        for (int k = 0; k < Kk; k++) m = fmaxf(m, pil_s[k]);
        float ss = 0.f;
        for (int k = 0; k < Kk; k++) ss += expf(pil_s[k] - m);
        g_logpi[t] = logf(expf(pil_s[t] - m) / ss + 1e-9f);
    }

    // B matrix [72][128], tf32-rounded
    for (int idx = t; idx < NB * 128; idx += 1024) {
        int n = idx >> 7, k = idx & 127;
        int d = k & 63, isq = k >> 6;
        float val = 0.f;
        if (n < Kk) {
            float lvc = fminf(fmaxf(q_logvar[n * Dd + d], -5.0f), 5.0f);
            float a   = phi_s[d] * expf(-lvc);
            float mu  = q_mu[n * Dd + d];
            if (isq) {
                val = a;
                obuf[n * Dd + d] = phi_s[d] * (LOG2PI_F + lvc) + mu * mu * a;
            } else {
                val = -2.0f * mu * a;
            }
            val = tf32r(val);
        } else if (n == Kk && isq) {
            val = tf32r(wbg_s[d]);    // background column (quadratic part)
        }
        g_Bmat[idx] = val;
    }
    __syncthreads();
    if (t < 64) {
        float s = 0.f;
        for (int d = 0; d < Dd; d++) s += obuf[t * Dd + d];
        g_offs[t] = -0.5f * s;
    }
}

// ---------------------------------------------------------------------------
// Kernel 2: fused main pass with mma.sync tf32 tensor cores.
// CTA = 128 rows; warp w owns rows 16w..16w+15 (one m16 tile, 9 n8 tiles).
// x^2 operand is squared in registers (only x staged in SMEM).
// ---------------------------------------------------------------------------
#define ASTR 68
#define BSTR 132
#define OFF_A    0
#define OFF_B    34816
#define OFF_OFFS 72832
#define OFF_LPI  73088
#define SMEM_BYTES 73344

__global__ void __launch_bounds__(TPB)
main_kernel(const float* __restrict__ X, float* __restrict__ out)
{
    extern __shared__ char smem[];
    float* A_s    = (float*)(smem + OFF_A);     // 128 x 68 (k=0..63 used)
    float* B_s    = (float*)(smem + OFF_B);     // 72 x 132
    float* offs_s = (float*)(smem + OFF_OFFS);
    float* lpi_s  = (float*)(smem + OFF_LPI);

    const int tid = threadIdx.x, wid = tid >> 5, lane = tid & 31;
    const int g = lane >> 2, t4 = lane & 3;
    const int n0 = blockIdx.x * TM;

    // stage B (72x128 -> stride 132) via float4
    #pragma unroll
    for (int it = 0; it < 9; it++) {
        int i4 = tid + TPB * it;   // 2304 float4s
        int n = i4 >> 5, kq = (i4 & 31) << 2;
        float4 v = *(const float4*)(g_Bmat + n * 128 + kq);
        *(float4*)(B_s + n * BSTR + kq) = v;
    }
    if (tid < 64) { offs_s[tid] = g_offs[tid]; lpi_s[tid] = g_logpi[tid]; }

    // stage X tile (128x64), tf32-rounded
    #pragma unroll
    for (int it = 0; it < 8; it++) {
        int i4 = tid + TPB * it;   // 2048 float4s
        int m = i4 >> 4, kq = (i4 & 15) << 2;
        float4 v = *(const float4*)(X + (size_t)(n0 + m) * Dd + kq);
        v.x = tf32r(v.x); v.y = tf32r(v.y); v.z = tf32r(v.z); v.w = tf32r(v.w);
        *(float4*)(A_s + m * ASTR + kq) = v;
    }
    __syncthreads();

    float c[9][4];
    #pragma unroll
    for (int j = 0; j < 9; j++)
        { c[j][0] = 0.f; c[j][1] = 0.f; c[j][2] = 0.f; c[j][3] = 0.f; }

    const float* aptr = A_s + (16 * wid + g) * ASTR + t4;

    #pragma unroll
    for (int k0 = 0; k0 < 64; k0 += 8) {
        float fa0 = aptr[k0];
        float fa1 = aptr[8 * ASTR + k0];
        float fa2 = aptr[k0 + 4];
        float fa3 = aptr[8 * ASTR + k0 + 4];
        uint32_t a0 = __float_as_uint(fa0), a1 = __float_as_uint(fa1);
        uint32_t a2 = __float_as_uint(fa2), a3 = __float_as_uint(fa3);
        uint32_t q0 = __float_as_uint(tf32r(fa0 * fa0));
        uint32_t q1 = __float_as_uint(tf32r(fa1 * fa1));
        uint32_t q2 = __float_as_uint(tf32r(fa2 * fa2));
        uint32_t q3 = __float_as_uint(tf32r(fa3 * fa3));
        #pragma unroll
        for (int j = 0; j < 9; j++) {
            const float* bb = B_s + (8 * j + g) * BSTR + t4;
            uint32_t b0 = __float_as_uint(bb[k0]);
            uint32_t b1 = __float_as_uint(bb[k0 + 4]);
            mma8(c[j], a0, a1, a2, a3, b0, b1);
            uint32_t e0 = __float_as_uint(bb[k0 + 64]);
            uint32_t e1 = __float_as_uint(bb[k0 + 68]);
            mma8(c[j], q0, q1, q2, q3, e0, e1);
        }
    }

    // ---------------- epilogue ----------------
    const float C0 = g_C0;
    double lsesum = 0.0;
    #pragma unroll
    for (int h = 0; h < 2; h++) {
        int r = 16 * wid + g + 8 * h;                  // local row
        float bgq  = __shfl_sync(0xffffffffu, c[8][2 * h], lane & ~3);
        float lpbg = -0.5f * (C0 + bgq);
        float lp[16];
        float mx = -3.4e38f;
        #pragma unroll
        for (int j = 0; j < 8; j++) {
            int col = 8 * j + 2 * t4;
            float v0 = fmaf(-0.5f, c[j][2 * h],     offs_s[col])     + lpbg;
            float v1 = fmaf(-0.5f, c[j][2 * h + 1], offs_s[col + 1]) + lpbg;
            lp[2 * j] = v0; lp[2 * j + 1] = v1;
            mx = fmaxf(mx, fmaxf(v0 + lpi_s[col], v1 + lpi_s[col + 1]));
        }
        mx = fmaxf(mx, __shfl_xor_sync(0xffffffffu, mx, 1));
        mx = fmaxf(mx, __shfl_xor_sync(0xffffffffu, mx, 2));
        float se = 0.f;
        #pragma unroll
        for (int j = 0; j < 8; j++) {
            int col = 8 * j + 2 * t4;
            se += __expf(lp[2 * j]     + lpi_s[col]     - mx);
            se += __expf(lp[2 * j + 1] + lpi_s[col + 1] - mx);
        }
        se += __shfl_xor_sync(0xffffffffu, se, 1);
        se += __shfl_xor_sync(0xffffffffu, se, 2);
        if (t4 == 0) lsesum += (double)(mx + __logf(se));
        // stage lp into this warp's own A rows (safe: each warp only ever
        // read its own 16 A rows, and is done with them)
        float* srow = A_s + r * ASTR + 2 * t4;
        #pragma unroll
        for (int j = 0; j < 8; j++)
            *(float2*)(srow + 8 * j) = make_float2(lp[2 * j], lp[2 * j + 1]);
    }

    // loss partial: warp reduce + one atomic per warp
    #pragma unroll
    for (int s = 16; s; s >>= 1)
        lsesum += __shfl_xor_sync(0xffffffffu, lsesum, s);
    if (lane == 0) atomicAdd(&g_lse, lsesum);

    __syncthreads();
    // coalesced copy of staged lp (out+65 is 4B-aligned only -> scalar)
    float* obase = out + 65 + (size_t)n0 * Kk;
    #pragma unroll
    for (int i = 0; i < 32; i++) {
        int idx = tid + TPB * i;                       // 8192 floats
        obase[idx] = A_s[(idx >> 6) * ASTR + (idx & 63)];
    }
}

// ---------------------------------------------------------------------------
__global__ void finalize_kernel(float* __restrict__ out)
{
    out[0] = (float)(g_kl - g_lse);
}

// ---------------------------------------------------------------------------
extern "C" void kernel_launch(void* const* d_in, const int* in_sizes, int n_in,
                              void* d_out, int out_size)
{
    const float* X  = (const float*)d_in[0];
    const float* u  = (const float*)d_in[1];
    const float* pl = (const float*)d_in[2];
    const float* mu = (const float*)d_in[3];
    const float* lv = (const float*)d_in[4];
    const float* pi = (const float*)d_in[5];
    const float* pp = (const float*)d_in[6];
    float* out = (float*)d_out;

    cudaFuncSetAttribute(main_kernel,
                         cudaFuncAttributeMaxDynamicSharedMemorySize, SMEM_BYTES);

    precompute_kernel<<<1, 1024>>>(u, pl, mu, lv, pi, pp, out);
    main_kernel<<<NTILES, TPB, SMEM_BYTES>>>(X, out);
    finalize_kernel<<<1, 1>>>(out);
}